// round 1
// baseline (speedup 1.0000x reference)
#include <cuda_runtime.h>
#include <cstdint>

#define Bz 4
#define S 1024
#define D 768
#define H 12
#define DK 64
#define BH (Bz*H)
#define NEGV -1e9f

// ---------------- scratch (device globals; no runtime allocation) ----------------
__device__ float g_Q[Bz*S*D];
__device__ float g_K[Bz*S*D];
__device__ float g_scores[(size_t)BH*S*S];     // 201 MB
__device__ float g_c1[Bz*S*D];
__device__ float g_c2[Bz*S*D];
__device__ float g_t1[Bz*S*D];
__device__ float g_t2[Bz*S*D];
__device__ float g_rmax[BH*S];
__device__ float g_rinv[BH*S];
__device__ float g_cmax[BH*S];
__device__ float g_cinv[BH*S];
__device__ int   g_mask_mode;                   // 0=i32, 1=u8, 2=f32

// ---------------- mask dtype sniffer (deterministic) ----------------
__global__ void detect_mask_kernel(const unsigned int* __restrict__ w) {
    __shared__ int s01, sf;
    if (threadIdx.x == 0) { s01 = 1; sf = 1; }
    __syncthreads();
    int a01 = 1, af = 1;
    for (int i = threadIdx.x; i < 4096; i += 256) {
        unsigned v = w[i];
        if (v != 0u && v != 1u) a01 = 0;
        if (v != 0u && v != 0x3F800000u) af = 0;
    }
    if (!a01) atomicAnd(&s01, 0);
    if (!af)  atomicAnd(&sf, 0);
    __syncthreads();
    if (threadIdx.x == 0) g_mask_mode = s01 ? 0 : (sf ? 2 : 1);
}

// ---------------- generic fp32 GEMM: C[M,N] = A[M,K] @ B[K,N] ----------------
// Tiles 64x64x16, 256 threads, 4x4 per thread. Requires M%64==0, N%64==0, K%16==0.
__global__ void gemm64_kernel(const float* __restrict__ A, const float* __restrict__ B,
                              float* __restrict__ C, int M, int N, int K) {
    __shared__ float As[64][17];   // [m][k], padded
    __shared__ float Bs[16][64];   // [k][n]
    int n0 = blockIdx.x * 64, m0 = blockIdx.y * 64;
    int tid = threadIdx.x;
    int tx = tid & 15, ty = tid >> 4;
    int ar = tid >> 2, ac = (tid & 3) * 4;
    int br = tid >> 4, bc = (tid & 15) * 4;
    float acc[4][4] = {};
    for (int k0 = 0; k0 < K; k0 += 16) {
        float4 va = *(const float4*)(A + (size_t)(m0 + ar) * K + k0 + ac);
        As[ar][ac] = va.x; As[ar][ac+1] = va.y; As[ar][ac+2] = va.z; As[ar][ac+3] = va.w;
        float4 vb = *(const float4*)(B + (size_t)(k0 + br) * N + n0 + bc);
        *(float4*)&Bs[br][bc] = vb;
        __syncthreads();
        #pragma unroll
        for (int kk = 0; kk < 16; kk++) {
            float bv[4];
            *(float4*)bv = *(const float4*)&Bs[kk][tx * 4];
            float a0 = As[ty*4+0][kk], a1 = As[ty*4+1][kk],
                  a2 = As[ty*4+2][kk], a3 = As[ty*4+3][kk];
            #pragma unroll
            for (int j = 0; j < 4; j++) {
                acc[0][j] += a0 * bv[j];
                acc[1][j] += a1 * bv[j];
                acc[2][j] += a2 * bv[j];
                acc[3][j] += a3 * bv[j];
            }
        }
        __syncthreads();
    }
    #pragma unroll
    for (int i = 0; i < 4; i++) {
        float4 o; o.x = acc[i][0]; o.y = acc[i][1]; o.z = acc[i][2]; o.w = acc[i][3];
        *(float4*)(C + (size_t)(m0 + ty*4 + i) * N + n0 + tx * 4) = o;
    }
}

// ---------------- scores[b,h,s,t] = (Q_h[s] . K_h[t]) / 8, masked ----------------
__global__ void scores_kernel(const float* __restrict__ Q, const float* __restrict__ Km,
                              const void* __restrict__ mask, float* __restrict__ sc) {
    __shared__ float Qs[64][65];  // [s][d]
    __shared__ float Ks[64][65];  // [t][d]
    int bh = blockIdx.z, b = bh / H, h = bh % H;
    int t0 = blockIdx.x * 64, s0 = blockIdx.y * 64;
    int tid = threadIdx.x;
    int mode = g_mask_mode;
    int c4 = (tid & 15) * 4;
    int r = tid >> 4;
    #pragma unroll
    for (int p = 0; p < 4; p++) {
        int rr = r + p * 16;
        float4 vq = *(const float4*)(Q + (size_t)(b * S + s0 + rr) * D + h * DK + c4);
        Qs[rr][c4] = vq.x; Qs[rr][c4+1] = vq.y; Qs[rr][c4+2] = vq.z; Qs[rr][c4+3] = vq.w;
        float4 vk = *(const float4*)(Km + (size_t)(b * S + t0 + rr) * D + h * DK + c4);
        Ks[rr][c4] = vk.x; Ks[rr][c4+1] = vk.y; Ks[rr][c4+2] = vk.z; Ks[rr][c4+3] = vk.w;
    }
    __syncthreads();
    int tx = tid & 15, ty = tid >> 4;
    float acc[4][4] = {};
    #pragma unroll
    for (int d = 0; d < 64; d++) {
        float a[4], bv[4];
        #pragma unroll
        for (int i = 0; i < 4; i++) a[i] = Qs[ty*4+i][d];
        #pragma unroll
        for (int j = 0; j < 4; j++) bv[j] = Ks[tx*4+j][d];
        #pragma unroll
        for (int i = 0; i < 4; i++)
            #pragma unroll
            for (int j = 0; j < 4; j++)
                acc[i][j] += a[i] * bv[j];
    }
    const unsigned char* m8 = (const unsigned char*)mask;
    const int* m32 = (const int*)mask;
    const float* mf = (const float*)mask;
    #pragma unroll
    for (int i = 0; i < 4; i++) {
        int s = s0 + ty*4 + i;
        #pragma unroll
        for (int j = 0; j < 4; j++) {
            int t = t0 + tx*4 + j;
            // mask1_2 is [B,H,t,s]; reference masks scores[s,t] with mask1_2[...,t,s]
            size_t midx = ((size_t)bh * S + t) * S + s;
            bool msk = (mode == 1) ? (m8[midx] != 0)
                     : (mode == 0) ? (m32[midx] != 0)
                                   : (mf[midx] != 0.0f);
            float v = msk ? NEGV : acc[i][j] * 0.125f;
            sc[((size_t)bh * S + s) * S + t] = v;
        }
    }
}

// ---------------- row softmax stats (over t, per [bh,s]) ----------------
__global__ void row_stats_kernel(const float* __restrict__ sc,
                                 float* __restrict__ rmax, float* __restrict__ rinv) {
    int bh = blockIdx.y, s = blockIdx.x;
    const float* row = sc + ((size_t)bh * S + s) * S;
    int tid = threadIdx.x;
    float4 v = *(const float4*)(row + tid * 4);
    float m = fmaxf(fmaxf(v.x, v.y), fmaxf(v.z, v.w));
    __shared__ float red[8];
    #pragma unroll
    for (int o = 16; o; o >>= 1) m = fmaxf(m, __shfl_xor_sync(0xffffffffu, m, o));
    if ((tid & 31) == 0) red[tid >> 5] = m;
    __syncthreads();
    float mm = red[0];
    #pragma unroll
    for (int i = 1; i < 8; i++) mm = fmaxf(mm, red[i]);
    float sum = __expf(v.x - mm) + __expf(v.y - mm) + __expf(v.z - mm) + __expf(v.w - mm);
    #pragma unroll
    for (int o = 16; o; o >>= 1) sum += __shfl_xor_sync(0xffffffffu, sum, o);
    __syncthreads();
    if ((tid & 31) == 0) red[tid >> 5] = sum;
    __syncthreads();
    if (tid == 0) {
        float t = 0.f;
        #pragma unroll
        for (int i = 0; i < 8; i++) t += red[i];
        rmax[bh * S + s] = mm;
        rinv[bh * S + s] = 1.0f / t;
    }
}

// ---------------- col softmax stats (over s, per [bh,t]) ----------------
__global__ void col_stats_kernel(const float* __restrict__ sc,
                                 float* __restrict__ cmax, float* __restrict__ cinv) {
    int bh = blockIdx.y;
    int t = blockIdx.x * 256 + threadIdx.x;
    const float* base = sc + (size_t)bh * S * S + t;
    float m = -1e30f;
    #pragma unroll 4
    for (int s = 0; s < S; s++) m = fmaxf(m, base[(size_t)s * S]);
    float sum = 0.f;
    #pragma unroll 4
    for (int s = 0; s < S; s++) sum += __expf(base[(size_t)s * S] - m);
    cmax[bh * S + t] = m;
    cinv[bh * S + t] = 1.0f / sum;
}

// ---------------- ctx1[b,s,h,:] = softmax_row(scores) @ K_h ----------------
__global__ void ctx1_kernel(const float* __restrict__ sc, const float* __restrict__ Km,
                            const float* __restrict__ rmax, const float* __restrict__ rinv,
                            float* __restrict__ C) {
    __shared__ float Ps[32][65];   // [t_local][s_local]
    __shared__ float Bs[32][64];   // [t_local][d]
    __shared__ float rm[64], ri[64];
    int bh = blockIdx.y, b = bh / H, h = bh % H;
    int s0 = blockIdx.x * 64;
    int tid = threadIdx.x;
    if (tid < 64) { rm[tid] = rmax[bh * S + s0 + tid]; ri[tid] = rinv[bh * S + s0 + tid]; }
    __syncthreads();
    int tx = tid & 15, ty = tid >> 4;
    float acc[4][4] = {};
    for (int t0 = 0; t0 < S; t0 += 32) {
        {
            int c4 = (tid & 7) * 4, sl = tid >> 3;
            #pragma unroll
            for (int p = 0; p < 2; p++) {
                int ss = sl + p * 32;
                float4 v = *(const float4*)(sc + ((size_t)bh * S + s0 + ss) * S + t0 + c4);
                float mx = rm[ss], iv = ri[ss];
                Ps[c4+0][ss] = __expf(v.x - mx) * iv;
                Ps[c4+1][ss] = __expf(v.y - mx) * iv;
                Ps[c4+2][ss] = __expf(v.z - mx) * iv;
                Ps[c4+3][ss] = __expf(v.w - mx) * iv;
            }
            int c4b = (tid & 15) * 4, tl = tid >> 4;
            #pragma unroll
            for (int p = 0; p < 2; p++) {
                int tt = tl + p * 16;
                float4 v = *(const float4*)(Km + (size_t)(b * S + t0 + tt) * D + h * DK + c4b);
                *(float4*)&Bs[tt][c4b] = v;
            }
        }
        __syncthreads();
        #pragma unroll
        for (int tt = 0; tt < 32; tt++) {
            float bv[4];
            *(float4*)bv = *(const float4*)&Bs[tt][tx * 4];
            float a0 = Ps[tt][ty*4+0], a1 = Ps[tt][ty*4+1],
                  a2 = Ps[tt][ty*4+2], a3 = Ps[tt][ty*4+3];
            #pragma unroll
            for (int j = 0; j < 4; j++) {
                acc[0][j] += a0 * bv[j];
                acc[1][j] += a1 * bv[j];
                acc[2][j] += a2 * bv[j];
                acc[3][j] += a3 * bv[j];
            }
        }
        __syncthreads();
    }
    #pragma unroll
    for (int i = 0; i < 4; i++) {
        float4 o; o.x = acc[i][0]; o.y = acc[i][1]; o.z = acc[i][2]; o.w = acc[i][3];
        *(float4*)(C + (size_t)(b * S + s0 + ty*4 + i) * D + h * DK + tx * 4) = o;
    }
}

// ---------------- ctx2[b,t,h,:] = softmax_col(scores)^T @ Q_h ----------------
__global__ void ctx2_kernel(const float* __restrict__ sc, const float* __restrict__ Q,
                            const float* __restrict__ cmax, const float* __restrict__ cinv,
                            float* __restrict__ C) {
    __shared__ float Ps[32][65];   // [s_local][t_local]
    __shared__ float Bs[32][64];   // [s_local][d]
    __shared__ float cm[64], ci[64];
    int bh = blockIdx.y, b = bh / H, h = bh % H;
    int t0 = blockIdx.x * 64;
    int tid = threadIdx.x;
    if (tid < 64) { cm[tid] = cmax[bh * S + t0 + tid]; ci[tid] = cinv[bh * S + t0 + tid]; }
    __syncthreads();
    int tx = tid & 15, ty = tid >> 4;
    float acc[4][4] = {};
    for (int s0 = 0; s0 < S; s0 += 32) {
        {
            int c4 = (tid & 15) * 4, sl = tid >> 4;
            #pragma unroll
            for (int p = 0; p < 2; p++) {
                int ss = sl + p * 16;
                float4 v = *(const float4*)(sc + ((size_t)bh * S + s0 + ss) * S + t0 + c4);
                Ps[ss][c4+0] = __expf(v.x - cm[c4+0]) * ci[c4+0];
                Ps[ss][c4+1] = __expf(v.y - cm[c4+1]) * ci[c4+1];
                Ps[ss][c4+2] = __expf(v.z - cm[c4+2]) * ci[c4+2];
                Ps[ss][c4+3] = __expf(v.w - cm[c4+3]) * ci[c4+3];
            }
            #pragma unroll
            for (int p = 0; p < 2; p++) {
                int ss = sl + p * 16;
                float4 v = *(const float4*)(Q + (size_t)(b * S + s0 + ss) * D + h * DK + c4);
                *(float4*)&Bs[ss][c4] = v;
            }
        }
        __syncthreads();
        #pragma unroll
        for (int ssi = 0; ssi < 32; ssi++) {
            float bv[4];
            *(float4*)bv = *(const float4*)&Bs[ssi][tx * 4];
            float a0 = Ps[ssi][ty*4+0], a1 = Ps[ssi][ty*4+1],
                  a2 = Ps[ssi][ty*4+2], a3 = Ps[ssi][ty*4+3];
            #pragma unroll
            for (int j = 0; j < 4; j++) {
                acc[0][j] += a0 * bv[j];
                acc[1][j] += a1 * bv[j];
                acc[2][j] += a2 * bv[j];
                acc[3][j] += a3 * bv[j];
            }
        }
        __syncthreads();
    }
    #pragma unroll
    for (int i = 0; i < 4; i++) {
        float4 o; o.x = acc[i][0]; o.y = acc[i][1]; o.z = acc[i][2]; o.w = acc[i][3];
        *(float4*)(C + (size_t)(b * S + t0 + ty*4 + i) * D + h * DK + tx * 4) = o;
    }
}

// ---------------- LayerNorm over last dim (768) ----------------
__global__ void ln_kernel(const float* __restrict__ x, const float* __restrict__ g,
                          const float* __restrict__ bb, float* __restrict__ out) {
    int row = blockIdx.x, tid = threadIdx.x;
    const float* xr = x + (size_t)row * D;
    float v0 = xr[tid], v1 = xr[tid + 256], v2 = xr[tid + 512];
    float s = v0 + v1 + v2;
    __shared__ float red[8];
    #pragma unroll
    for (int o = 16; o; o >>= 1) s += __shfl_xor_sync(0xffffffffu, s, o);
    if ((tid & 31) == 0) red[tid >> 5] = s;
    __syncthreads();
    float tot = 0.f;
    #pragma unroll
    for (int i = 0; i < 8; i++) tot += red[i];
    float mu = tot * (1.0f / 768.0f);
    float d0 = v0 - mu, d1 = v1 - mu, d2 = v2 - mu;
    float q = d0 * d0 + d1 * d1 + d2 * d2;
    #pragma unroll
    for (int o = 16; o; o >>= 1) q += __shfl_xor_sync(0xffffffffu, q, o);
    __syncthreads();
    if ((tid & 31) == 0) red[tid >> 5] = q;
    __syncthreads();
    float var = 0.f;
    #pragma unroll
    for (int i = 0; i < 8; i++) var += red[i];
    var *= (1.0f / 768.0f);
    float rs = rsqrtf(var + 1e-5f);
    float* orow = out + (size_t)row * D;
    orow[tid]       = d0 * rs * g[tid]       + bb[tid];
    orow[tid + 256] = d1 * rs * g[tid + 256] + bb[tid + 256];
    orow[tid + 512] = d2 * rs * g[tid + 512] + bb[tid + 512];
}

// ---------------- launch ----------------
extern "C" void kernel_launch(void* const* d_in, const int* in_sizes, int n_in,
                              void* d_out, int out_size) {
    const float* pro1 = (const float*)d_in[0];
    const float* pro2 = (const float*)d_in[1];
    const void*  mask = d_in[2];
    const float* W_Q  = (const float*)d_in[3];
    const float* W_K  = (const float*)d_in[4];
    const float* fc1  = (const float*)d_in[5];
    const float* g1   = (const float*)d_in[6];
    const float* b1   = (const float*)d_in[7];
    const float* g2   = (const float*)d_in[8];
    const float* b2   = (const float*)d_in[9];
    float* out = (float*)d_out;

    float *Qp, *Kp, *Sp, *C1, *C2, *T1, *T2, *RM, *RI, *CM, *CI;
    cudaGetSymbolAddress((void**)&Qp, g_Q);
    cudaGetSymbolAddress((void**)&Kp, g_K);
    cudaGetSymbolAddress((void**)&Sp, g_scores);
    cudaGetSymbolAddress((void**)&C1, g_c1);
    cudaGetSymbolAddress((void**)&C2, g_c2);
    cudaGetSymbolAddress((void**)&T1, g_t1);
    cudaGetSymbolAddress((void**)&T2, g_t2);
    cudaGetSymbolAddress((void**)&RM, g_rmax);
    cudaGetSymbolAddress((void**)&RI, g_rinv);
    cudaGetSymbolAddress((void**)&CM, g_cmax);
    cudaGetSymbolAddress((void**)&CI, g_cinv);

    detect_mask_kernel<<<1, 256>>>((const unsigned int*)mask);

    dim3 gProj(D / 64, (Bz * S) / 64);
    gemm64_kernel<<<gProj, 256>>>(pro1, W_Q, Qp, Bz * S, D, D);
    gemm64_kernel<<<gProj, 256>>>(pro2, W_K, Kp, Bz * S, D, D);

    scores_kernel<<<dim3(S / 64, S / 64, BH), 256>>>(Qp, Kp, mask, Sp);

    row_stats_kernel<<<dim3(S, BH), 256>>>(Sp, RM, RI);
    col_stats_kernel<<<dim3(S / 256, BH), 256>>>(Sp, CM, CI);

    ctx1_kernel<<<dim3(S / 64, BH), 256>>>(Sp, Kp, RM, RI, C1);
    ctx2_kernel<<<dim3(S / 64, BH), 256>>>(Sp, Qp, CM, CI, C2);

    gemm64_kernel<<<gProj, 256>>>(C1, fc1, T1, Bz * S, D, D);
    gemm64_kernel<<<gProj, 256>>>(C2, fc1, T2, Bz * S, D, D);

    ln_kernel<<<Bz * S, 256>>>(T1, g1, b1, out);
    ln_kernel<<<Bz * S, 256>>>(T2, g2, b2, out + (size_t)Bz * S * D);
}

// round 2
// speedup vs baseline: 2.3096x; 2.3096x over previous
#include <cuda_runtime.h>
#include <cstdint>

#define Bz 4
#define S 1024
#define D 768
#define H 12
#define DK 64
#define BH (Bz*H)
#define NEGV -1e9f

// ---------------- scratch (device globals) ----------------
__device__ float g_Q[Bz*S*D];
__device__ float g_K[Bz*S*D];
__device__ float g_QT[BH*DK*S];
__device__ float g_KT[BH*DK*S];
__device__ float g_sc[(size_t)BH*S*S];     // scores TRANSPOSED: [bh][t][s]
__device__ float g_c1[Bz*S*D];
__device__ float g_c2[Bz*S*D];
__device__ float g_t1[Bz*S*D];
__device__ float g_t2[Bz*S*D];
__device__ float g_rmax[BH*S];  // softmax over t (for each s)
__device__ float g_rinv[BH*S];
__device__ float g_cmax[BH*S];  // softmax over s (for each t)
__device__ float g_cinv[BH*S];
__device__ int   g_mask_mode;   // 0=i32, 1=u8, 2=f32

// ---------------- helpers ----------------
__device__ __forceinline__ unsigned tf32c(float x) {
    unsigned u; asm("cvt.rna.tf32.f32 %0, %1;" : "=r"(u) : "f"(x)); return u;
}
__device__ __forceinline__ void mma8(float c[4], const unsigned a[4], const unsigned b[2]) {
    asm volatile(
        "mma.sync.aligned.m16n8k8.row.col.f32.tf32.tf32.f32 "
        "{%0,%1,%2,%3},{%4,%5,%6,%7},{%8,%9},{%0,%1,%2,%3};\n"
        : "+f"(c[0]), "+f"(c[1]), "+f"(c[2]), "+f"(c[3])
        : "r"(a[0]), "r"(a[1]), "r"(a[2]), "r"(a[3]), "r"(b[0]), "r"(b[1]));
}
__device__ __forceinline__ int kperm(int k) {  // within-chunk k (0..31) -> permuted slot
    return (k & ~7) + 2 * (k & 3) + ((k & 7) >> 2);
}

// ---------------- mask dtype sniffer ----------------
__global__ void detect_mask_kernel(const unsigned int* __restrict__ w) {
    __shared__ int s01, sf;
    if (threadIdx.x == 0) { s01 = 1; sf = 1; }
    __syncthreads();
    int a01 = 1, af = 1;
    for (int i = threadIdx.x; i < 4096; i += 256) {
        unsigned v = w[i];
        if (v != 0u && v != 1u) a01 = 0;
        if (v != 0u && v != 0x3F800000u) af = 0;
    }
    if (!a01) atomicAnd(&s01, 0);
    if (!af)  atomicAnd(&sf, 0);
    __syncthreads();
    if (threadIdx.x == 0) g_mask_mode = s01 ? 0 : (sf ? 2 : 1);
}

// ---------------- tf32 GEMM 128x128x32: C[4096,768] = A[4096,768] @ B[768,768] ----------------
__global__ void __launch_bounds__(256) mm128_kernel(const float* __restrict__ A,
                                                    const float* __restrict__ B,
                                                    float* __restrict__ C) {
    __shared__ unsigned As[128 * 36];
    __shared__ unsigned Bs[32 * 132];
    const int m0 = blockIdx.y * 128, n0 = blockIdx.x * 128;
    const int tid = threadIdx.x, lane = tid & 31, w = tid >> 5;
    const int g = lane >> 2, tq = lane & 3;
    const int mw = (w & 1) * 64, nw = (w >> 1) * 32;
    float c[16][4] = {};
    for (int k0 = 0; k0 < 768; k0 += 32) {
        {   // A: 128x32
            int kq = tid & 7, kc = kq * 4, bkp = (kq >> 1) * 8 + (kq & 1);
            #pragma unroll
            for (int it = 0; it < 4; it++) {
                int m = (tid >> 3) + it * 32;
                float4 v = *(const float4*)(A + (size_t)(m0 + m) * 768 + k0 + kc);
                unsigned* dst = &As[m * 36 + bkp];
                dst[0] = tf32c(v.x); dst[2] = tf32c(v.y); dst[4] = tf32c(v.z); dst[6] = tf32c(v.w);
            }
        }
        {   // B: 32x128 (row-major k x n)
            #pragma unroll
            for (int it = 0; it < 4; it++) {
                int kr = (tid >> 5) + it * 8;
                int nc = lane * 4;
                float4 v = *(const float4*)(B + (size_t)(k0 + kr) * 768 + n0 + nc);
                uint4 u; u.x = tf32c(v.x); u.y = tf32c(v.y); u.z = tf32c(v.z); u.w = tf32c(v.w);
                *(uint4*)&Bs[kperm(kr) * 132 + nc] = u;
            }
        }
        __syncthreads();
        #pragma unroll
        for (int ks = 0; ks < 4; ks++) {
            unsigned a[4][4], bf[4][2];
            #pragma unroll
            for (int i = 0; i < 4; i++) {
                int r = mw + 16 * i + g;
                uint2 x = *(const uint2*)&As[r * 36 + ks * 8 + 2 * tq];
                uint2 y = *(const uint2*)&As[(r + 8) * 36 + ks * 8 + 2 * tq];
                a[i][0] = x.x; a[i][1] = y.x; a[i][2] = x.y; a[i][3] = y.y;
            }
            #pragma unroll
            for (int j = 0; j < 4; j++) {
                int col = nw + 8 * j + g;
                bf[j][0] = Bs[(ks * 8 + 2 * tq) * 132 + col];
                bf[j][1] = Bs[(ks * 8 + 2 * tq + 1) * 132 + col];
            }
            #pragma unroll
            for (int i = 0; i < 4; i++)
                #pragma unroll
                for (int j = 0; j < 4; j++) mma8(c[i * 4 + j], a[i], bf[j]);
        }
        __syncthreads();
    }
    #pragma unroll
    for (int i = 0; i < 4; i++) {
        int r = m0 + mw + 16 * i + g;
        #pragma unroll
        for (int j = 0; j < 4; j++) {
            int col = n0 + nw + 8 * j + 2 * tq;
            *(float2*)(C + (size_t)r * 768 + col)       = make_float2(c[i*4+j][0], c[i*4+j][1]);
            *(float2*)(C + (size_t)(r + 8) * 768 + col) = make_float2(c[i*4+j][2], c[i*4+j][3]);
        }
    }
}

// ---------------- head transpose: X[b][s][h*64+d] -> XT[bh][d][s] ----------------
__global__ void tr_kernel(const float* __restrict__ X, float* __restrict__ XT) {
    __shared__ float tile[32][33];
    int bh = blockIdx.z, b = bh / H, h = bh % H;
    int s0 = blockIdx.x * 32, d0 = blockIdx.y * 32;
    int tx = threadIdx.x, ty = threadIdx.y;
    #pragma unroll
    for (int i = 0; i < 4; i++)
        tile[ty + 8 * i][tx] = X[(size_t)(b * S + s0 + ty + 8 * i) * D + h * DK + d0 + tx];
    __syncthreads();
    #pragma unroll
    for (int i = 0; i < 4; i++)
        XT[(size_t)(bh * DK + d0 + ty + 8 * i) * S + s0 + tx] = tile[tx][ty + 8 * i];
}

// ---------------- scoresT[bh][t][s] = (K_t . Q_s)/8, masked ----------------
__global__ void __launch_bounds__(256) scoresT_kernel(const float* __restrict__ Kmat,
                                                      const float* __restrict__ QT,
                                                      const void* __restrict__ mask,
                                                      float* __restrict__ scT) {
    __shared__ unsigned As[128 * 36];
    __shared__ unsigned Bs[32 * 132];
    const int bh = blockIdx.z, b = bh / H, h = bh % H;
    const int s0 = blockIdx.x * 128, t0 = blockIdx.y * 128;
    const float* Ag = Kmat + (size_t)(b * S + t0) * D + h * DK;  // rows=t, cols=d
    const float* Bg = QT + (size_t)bh * DK * S + s0;             // rows=d, cols=s
    const int tid = threadIdx.x, lane = tid & 31, w = tid >> 5;
    const int g = lane >> 2, tq = lane & 3;
    const int mw = (w & 1) * 64, nw = (w >> 1) * 32;
    float c[16][4] = {};
    #pragma unroll
    for (int k0 = 0; k0 < 64; k0 += 32) {
        {
            int kq = tid & 7, kc = kq * 4, bkp = (kq >> 1) * 8 + (kq & 1);
            #pragma unroll
            for (int it = 0; it < 4; it++) {
                int m = (tid >> 3) + it * 32;
                float4 v = *(const float4*)(Ag + (size_t)m * D + k0 + kc);
                unsigned* dst = &As[m * 36 + bkp];
                dst[0] = tf32c(v.x); dst[2] = tf32c(v.y); dst[4] = tf32c(v.z); dst[6] = tf32c(v.w);
            }
        }
        {
            #pragma unroll
            for (int it = 0; it < 4; it++) {
                int kr = (tid >> 5) + it * 8;
                int nc = lane * 4;
                float4 v = *(const float4*)(Bg + (size_t)(k0 + kr) * S + nc);
                uint4 u; u.x = tf32c(v.x); u.y = tf32c(v.y); u.z = tf32c(v.z); u.w = tf32c(v.w);
                *(uint4*)&Bs[kperm(kr) * 132 + nc] = u;
            }
        }
        __syncthreads();
        #pragma unroll
        for (int ks = 0; ks < 4; ks++) {
            unsigned a[4][4], bf[4][2];
            #pragma unroll
            for (int i = 0; i < 4; i++) {
                int r = mw + 16 * i + g;
                uint2 x = *(const uint2*)&As[r * 36 + ks * 8 + 2 * tq];
                uint2 y = *(const uint2*)&As[(r + 8) * 36 + ks * 8 + 2 * tq];
                a[i][0] = x.x; a[i][1] = y.x; a[i][2] = x.y; a[i][3] = y.y;
            }
            #pragma unroll
            for (int j = 0; j < 4; j++) {
                int col = nw + 8 * j + g;
                bf[j][0] = Bs[(ks * 8 + 2 * tq) * 132 + col];
                bf[j][1] = Bs[(ks * 8 + 2 * tq + 1) * 132 + col];
            }
            #pragma unroll
            for (int i = 0; i < 4; i++)
                #pragma unroll
                for (int j = 0; j < 4; j++) mma8(c[i * 4 + j], a[i], bf[j]);
        }
        __syncthreads();
    }
    // masked epilogue: scT and mask share [bh][t][s] layout
    const int mode = g_mask_mode;
    const int* m32 = (const int*)mask;
    const unsigned char* m8 = (const unsigned char*)mask;
    const float* mf = (const float*)mask;
    #pragma unroll
    for (int i = 0; i < 4; i++) {
        int rA = t0 + mw + 16 * i + g;
        #pragma unroll
        for (int j = 0; j < 4; j++) {
            int cs = s0 + nw + 8 * j + 2 * tq;
            float* cc = c[i * 4 + j];
            size_t iA = ((size_t)bh * S + rA) * S + cs;
            size_t iB = iA + (size_t)8 * S;
            float2 o0 = make_float2(cc[0] * 0.125f, cc[1] * 0.125f);
            float2 o1 = make_float2(cc[2] * 0.125f, cc[3] * 0.125f);
            if (mode == 0) {
                int2 qa = *(const int2*)(m32 + iA); int2 qb = *(const int2*)(m32 + iB);
                if (qa.x) o0.x = NEGV; if (qa.y) o0.y = NEGV;
                if (qb.x) o1.x = NEGV; if (qb.y) o1.y = NEGV;
            } else if (mode == 1) {
                uchar2 qa = *(const uchar2*)(m8 + iA); uchar2 qb = *(const uchar2*)(m8 + iB);
                if (qa.x) o0.x = NEGV; if (qa.y) o0.y = NEGV;
                if (qb.x) o1.x = NEGV; if (qb.y) o1.y = NEGV;
            } else {
                float2 qa = *(const float2*)(mf + iA); float2 qb = *(const float2*)(mf + iB);
                if (qa.x != 0.0f) o0.x = NEGV; if (qa.y != 0.0f) o0.y = NEGV;
                if (qb.x != 0.0f) o1.x = NEGV; if (qb.y != 0.0f) o1.y = NEGV;
            }
            *(float2*)(scT + iA) = o0;
            *(float2*)(scT + iB) = o1;
        }
    }
}

// ---------------- softmax stats over t (per s): column walk of scT ----------------
__global__ void row_stats_kernel(const float* __restrict__ scT,
                                 float* __restrict__ rmax, float* __restrict__ rinv) {
    int bh = blockIdx.y;
    int s = blockIdx.x * 256 + threadIdx.x;
    const float* p = scT + (size_t)bh * S * S + s;
    float m = -1e30f, sum = 0.f;
    for (int t = 0; t < S; t++) {
        float x = p[(size_t)t << 10];
        float mn = fmaxf(m, x);
        sum = sum * __expf(m - mn) + __expf(x - mn);
        m = mn;
    }
    rmax[bh * S + s] = m;
    rinv[bh * S + s] = 1.0f / sum;
}

// ---------------- softmax stats over s (per t): row reduce of scT ----------------
__global__ void col_stats_kernel(const float* __restrict__ scT,
                                 float* __restrict__ cmax, float* __restrict__ cinv) {
    int bh = blockIdx.y;
    int t = blockIdx.x * 8 + (threadIdx.x >> 5);
    int lane = threadIdx.x & 31;
    const float4* p = (const float4*)(scT + ((size_t)bh * S + t) * S) + lane;
    float4 v[8];
    #pragma unroll
    for (int i = 0; i < 8; i++) v[i] = p[i * 32];
    float m = -1e30f;
    #pragma unroll
    for (int i = 0; i < 8; i++)
        m = fmaxf(m, fmaxf(fmaxf(v[i].x, v[i].y), fmaxf(v[i].z, v[i].w)));
    #pragma unroll
    for (int o = 16; o; o >>= 1) m = fmaxf(m, __shfl_xor_sync(0xffffffffu, m, o));
    float sum = 0.f;
    #pragma unroll
    for (int i = 0; i < 8; i++)
        sum += __expf(v[i].x - m) + __expf(v[i].y - m) + __expf(v[i].z - m) + __expf(v[i].w - m);
    #pragma unroll
    for (int o = 16; o; o >>= 1) sum += __shfl_xor_sync(0xffffffffu, sum, o);
    if (lane == 0) { cmax[bh * S + t] = m; cinv[bh * S + t] = 1.0f / sum; }
}

// ---------------- ctx1: c1[b][s][h,d] = sum_t P1[s][t] * K[t][d]  (computed as KT @ P1) ----------------
// m=d(64), n=s(256), k=t
__global__ void __launch_bounds__(256) ctx1_kernel(const float* __restrict__ KT,
                                                   const float* __restrict__ scT,
                                                   const float* __restrict__ rmax,
                                                   const float* __restrict__ rinv,
                                                   float* __restrict__ C) {
    __shared__ unsigned As[64 * 36];
    __shared__ unsigned Bs[32 * 268];
    __shared__ float rms[256], ris[256];
    const int bh = blockIdx.y, b = bh / H, h = bh % H;
    const int s0 = blockIdx.x * 256;
    const float* Ag = KT + (size_t)bh * DK * S;                 // rows=d, cols=t
    const float* Bg = scT + (size_t)bh * S * S + s0;            // rows=t, cols=s
    const int tid = threadIdx.x, lane = tid & 31, w = tid >> 5;
    const int g = lane >> 2, tq = lane & 3;
    const int nw = w * 32;
    rms[tid] = rmax[bh * S + s0 + tid];
    ris[tid] = rinv[bh * S + s0 + tid];
    __syncthreads();
    float c[16][4] = {};
    for (int k0 = 0; k0 < S; k0 += 32) {
        {   // A: 64 x 32 from KT rows
            int kq = tid & 7, kc = kq * 4, bkp = (kq >> 1) * 8 + (kq & 1);
            #pragma unroll
            for (int it = 0; it < 2; it++) {
                int m = (tid >> 3) + it * 32;
                float4 v = *(const float4*)(Ag + (size_t)m * S + k0 + kc);
                unsigned* dst = &As[m * 36 + bkp];
                dst[0] = tf32c(v.x); dst[2] = tf32c(v.y); dst[4] = tf32c(v.z); dst[6] = tf32c(v.w);
            }
        }
        {   // B: 32 x 256 = P1 rows (exp applied)
            #pragma unroll
            for (int it = 0; it < 8; it++) {
                int kr = (tid >> 6) + it * 4;
                int nc = (tid & 63) * 4;
                float4 v = *(const float4*)(Bg + (size_t)(k0 + kr) * S + nc);
                uint4 u;
                u.x = tf32c(__expf(v.x - rms[nc + 0]) * ris[nc + 0]);
                u.y = tf32c(__expf(v.y - rms[nc + 1]) * ris[nc + 1]);
                u.z = tf32c(__expf(v.z - rms[nc + 2]) * ris[nc + 2]);
                u.w = tf32c(__expf(v.w - rms[nc + 3]) * ris[nc + 3]);
                *(uint4*)&Bs[kperm(kr) * 268 + nc] = u;
            }
        }
        __syncthreads();
        #pragma unroll
        for (int ks = 0; ks < 4; ks++) {
            unsigned a[4][4], bf[4][2];
            #pragma unroll
            for (int i = 0; i < 4; i++) {
                int r = 16 * i + g;
                uint2 x = *(const uint2*)&As[r * 36 + ks * 8 + 2 * tq];
                uint2 y = *(const uint2*)&As[(r + 8) * 36 + ks * 8 + 2 * tq];
                a[i][0] = x.x; a[i][1] = y.x; a[i][2] = x.y; a[i][3] = y.y;
            }
            #pragma unroll
            for (int j = 0; j < 4; j++) {
                int col = nw + 8 * j + g;
                bf[j][0] = Bs[(ks * 8 + 2 * tq) * 268 + col];
                bf[j][1] = Bs[(ks * 8 + 2 * tq + 1) * 268 + col];
            }
            #pragma unroll
            for (int i = 0; i < 4; i++)
                #pragma unroll
                for (int j = 0; j < 4; j++) mma8(c[i * 4 + j], a[i], bf[j]);
        }
        __syncthreads();
    }
    // epilogue: frag (row=d, col=s) -> C[b][s][h*64+d]
    #pragma unroll
    for (int i = 0; i < 4; i++) {
        int d = 16 * i + g;
        #pragma unroll
        for (int j = 0; j < 4; j++) {
            int s = s0 + nw + 8 * j + 2 * tq;
            float* cc = c[i * 4 + j];
            size_t a0 = (size_t)(b * S + s) * D + h * DK + d;
            C[a0]         = cc[0];
            C[a0 + D]     = cc[1];
            C[a0 + 8]     = cc[2];
            C[a0 + D + 8] = cc[3];
        }
    }
}

// ---------------- ctx2: c2[b][t][h,d] = sum_s P2[t][s] * Q[s][d] ----------------
// m=t(256), n=d(64), k=s
__global__ void __launch_bounds__(256) ctx2_kernel(const float* __restrict__ scT,
                                                   const float* __restrict__ Q,
                                                   const float* __restrict__ cmax,
                                                   const float* __restrict__ cinv,
                                                   float* __restrict__ C) {
    __shared__ unsigned As[256 * 36];
    __shared__ unsigned Bs[32 * 68];
    __shared__ float cms[256], cis[256];
    const int bh = blockIdx.y, b = bh / H, h = bh % H;
    const int t0 = blockIdx.x * 256;
    const float* Ag = scT + ((size_t)bh * S + t0) * S;          // rows=t, cols=s
    const float* Bg = Q + (size_t)b * S * D + h * DK;           // rows=s, cols=d
    const int tid = threadIdx.x, lane = tid & 31, w = tid >> 5;
    const int g = lane >> 2, tq = lane & 3;
    const int mw = (w >> 1) * 64, nw = (w & 1) * 32;
    cms[tid] = cmax[bh * S + t0 + tid];
    cis[tid] = cinv[bh * S + t0 + tid];
    __syncthreads();
    float c[16][4] = {};
    for (int k0 = 0; k0 < S; k0 += 32) {
        {   // A: 256 x 32 = P2 (exp applied per row)
            int kq = tid & 7, kc = kq * 4, bkp = (kq >> 1) * 8 + (kq & 1);
            #pragma unroll
            for (int it = 0; it < 8; it++) {
                int m = (tid >> 3) + it * 32;
                float4 v = *(const float4*)(Ag + (size_t)m * S + k0 + kc);
                float cm = cms[m], ci = cis[m];
                unsigned* dst = &As[m * 36 + bkp];
                dst[0] = tf32c(__expf(v.x - cm) * ci);
                dst[2] = tf32c(__expf(v.y - cm) * ci);
                dst[4] = tf32c(__expf(v.z - cm) * ci);
                dst[6] = tf32c(__expf(v.w - cm) * ci);
            }
        }
        {   // B: 32 x 64 from Q rows
            #pragma unroll
            for (int it = 0; it < 2; it++) {
                int kr = (tid >> 4) + it * 16;
                int nc = (tid & 15) * 4;
                float4 v = *(const float4*)(Bg + (size_t)(k0 + kr) * D + nc);
                uint4 u; u.x = tf32c(v.x); u.y = tf32c(v.y); u.z = tf32c(v.z); u.w = tf32c(v.w);
                *(uint4*)&Bs[kperm(kr) * 68 + nc] = u;
            }
        }
        __syncthreads();
        #pragma unroll
        for (int ks = 0; ks < 4; ks++) {
            unsigned a[4][4], bf[2][2];
            #pragma unroll
            for (int i = 0; i < 4; i++) {
                int r = mw + 16 * i + g;
                uint2 x = *(const uint2*)&As[r * 36 + ks * 8 + 2 * tq];
                uint2 y = *(const uint2*)&As[(r + 8) * 36 + ks * 8 + 2 * tq];
                a[i][0] = x.x; a[i][1] = y.x; a[i][2] = x.y; a[i][3] = y.y;
            }
            #pragma unroll
            for (int j = 0; j < 4; j++) {
                int col = nw + 8 * j + g;
                bf[j & 1][0] = Bs[(ks * 8 + 2 * tq) * 68 + col];
                bf[j & 1][1] = Bs[(ks * 8 + 2 * tq + 1) * 68 + col];
                // immediately consume to keep reg pressure low
                if (j & 1) {} // no-op
                #pragma unroll
                for (int i = 0; i < 4; i++) mma8(c[i * 4 + j], a[i], bf[j & 1]);
            }
        }
        __syncthreads();
    }
    #pragma unroll
    for (int i = 0; i < 4; i++) {
        int t = t0 + mw + 16 * i + g;
        #pragma unroll
        for (int j = 0; j < 4; j++) {
            int dcol = nw + 8 * j + 2 * tq;
            float* cc = c[i * 4 + j];
            size_t a0 = (size_t)(b * S + t) * D + h * DK + dcol;
            *(float2*)(C + a0)                 = make_float2(cc[0], cc[1]);
            *(float2*)(C + a0 + (size_t)8 * D) = make_float2(cc[2], cc[3]);
        }
    }
}

// ---------------- LayerNorm over last dim (768) ----------------
__global__ void ln_kernel(const float* __restrict__ x, const float* __restrict__ gg,
                          const float* __restrict__ bb, float* __restrict__ out) {
    int row = blockIdx.x, tid = threadIdx.x;
    const float* xr = x + (size_t)row * D;
    float v0 = xr[tid], v1 = xr[tid + 256], v2 = xr[tid + 512];
    float s = v0 + v1 + v2;
    __shared__ float red[8];
    #pragma unroll
    for (int o = 16; o; o >>= 1) s += __shfl_xor_sync(0xffffffffu, s, o);
    if ((tid & 31) == 0) red[tid >> 5] = s;
    __syncthreads();
    float tot = 0.f;
    #pragma unroll
    for (int i = 0; i < 8; i++) tot += red[i];
    float mu = tot * (1.0f / 768.0f);
    float d0 = v0 - mu, d1 = v1 - mu, d2 = v2 - mu;
    float q = d0 * d0 + d1 * d1 + d2 * d2;
    #pragma unroll
    for (int o = 16; o; o >>= 1) q += __shfl_xor_sync(0xffffffffu, q, o);
    __syncthreads();
    if ((tid & 31) == 0) red[tid >> 5] = q;
    __syncthreads();
    float var = 0.f;
    #pragma unroll
    for (int i = 0; i < 8; i++) var += red[i];
    var *= (1.0f / 768.0f);
    float rs = rsqrtf(var + 1e-5f);
    float* orow = out + (size_t)row * D;
    orow[tid]       = d0 * rs * gg[tid]       + bb[tid];
    orow[tid + 256] = d1 * rs * gg[tid + 256] + bb[tid + 256];
    orow[tid + 512] = d2 * rs * gg[tid + 512] + bb[tid + 512];
}

// ---------------- launch ----------------
extern "C" void kernel_launch(void* const* d_in, const int* in_sizes, int n_in,
                              void* d_out, int out_size) {
    const float* pro1 = (const float*)d_in[0];
    const float* pro2 = (const float*)d_in[1];
    const void*  mask = d_in[2];
    const float* W_Q  = (const float*)d_in[3];
    const float* W_K  = (const float*)d_in[4];
    const float* fc1  = (const float*)d_in[5];
    const float* g1   = (const float*)d_in[6];
    const float* b1   = (const float*)d_in[7];
    const float* g2   = (const float*)d_in[8];
    const float* b2   = (const float*)d_in[9];
    float* out = (float*)d_out;

    float *Qp, *Kp, *QTp, *KTp, *Sp, *C1, *C2, *T1, *T2, *RM, *RI, *CM, *CI;
    cudaGetSymbolAddress((void**)&Qp, g_Q);
    cudaGetSymbolAddress((void**)&Kp, g_K);
    cudaGetSymbolAddress((void**)&QTp, g_QT);
    cudaGetSymbolAddress((void**)&KTp, g_KT);
    cudaGetSymbolAddress((void**)&Sp, g_sc);
    cudaGetSymbolAddress((void**)&C1, g_c1);
    cudaGetSymbolAddress((void**)&C2, g_c2);
    cudaGetSymbolAddress((void**)&T1, g_t1);
    cudaGetSymbolAddress((void**)&T2, g_t2);
    cudaGetSymbolAddress((void**)&RM, g_rmax);
    cudaGetSymbolAddress((void**)&RI, g_rinv);
    cudaGetSymbolAddress((void**)&CM, g_cmax);
    cudaGetSymbolAddress((void**)&CI, g_cinv);

    detect_mask_kernel<<<1, 256>>>((const unsigned int*)mask);

    dim3 gProj(6, 32);  // N/128, M/128
    mm128_kernel<<<gProj, 256>>>(pro1, W_Q, Qp);
    mm128_kernel<<<gProj, 256>>>(pro2, W_K, Kp);

    tr_kernel<<<dim3(32, 2, BH), dim3(32, 8)>>>(Qp, QTp);
    tr_kernel<<<dim3(32, 2, BH), dim3(32, 8)>>>(Kp, KTp);

    scoresT_kernel<<<dim3(8, 8, BH), 256>>>(Kp, QTp, mask, Sp);

    row_stats_kernel<<<dim3(4, BH), 256>>>(Sp, RM, RI);
    col_stats_kernel<<<dim3(128, BH), 256>>>(Sp, CM, CI);

    ctx1_kernel<<<dim3(4, BH), 256>>>(KTp, Sp, RM, RI, C1);
    ctx2_kernel<<<dim3(4, BH), 256>>>(Sp, Qp, CM, CI, C2);

    mm128_kernel<<<gProj, 256>>>(C1, fc1, T1);
    mm128_kernel<<<gProj, 256>>>(C2, fc1, T2);

    ln_kernel<<<Bz * S, 256>>>(T1, g1, b1, out);
    ln_kernel<<<Bz * S, 256>>>(T2, g2, b2, out + (size_t)Bz * S * D);
}